// round 2
// baseline (speedup 1.0000x reference)
#include <cuda_runtime.h>

// Problem constants
#define T_STEPS  4
#define P_DIM    63
#define D_DIM    128
#define BN_ROWS  65536              // B*N = 64*1024
#define M_TOTAL  262144             // T*B*N
#define N_TILES  4096               // M_TOTAL / 64

// Scratch (no allocations allowed -> __device__ globals)
__device__ double g_C[64 * 64];     // S = sum_m x_m x_m^T  (cols 63 padded with zeros)
__device__ double g_colsum[64];     // per-feature column sums of x
__device__ float4 g_prm[D_DIM];     // per-channel (mean, rsqrt(var+eps), gamma, beta)

// ---------------------------------------------------------------------------
// Kernel 0: zero the stat accumulators (must run every launch: graph replays)
// ---------------------------------------------------------------------------
__global__ void zero_stats_kernel() {
    int i = blockIdx.x * blockDim.x + threadIdx.x;
    if (i < 64 * 64) g_C[i] = 0.0;
    if (i < 64)      g_colsum[i] = 0.0;
}

// ---------------------------------------------------------------------------
// Kernel 1: stats pass.  S += X^T X  and colsum += X^T 1 over all M rows.
// Block: 256 threads, each thread owns a 4x4 tile of the 64x64 S matrix.
// Per tile: 64 rows of x staged in smem (col 63 zero-padded).
// ---------------------------------------------------------------------------
__global__ __launch_bounds__(256) void stats_kernel(const float* __restrict__ x) {
    __shared__ __align__(16) float xs[64][64];
    const int tid = threadIdx.x;
    const int ti = tid >> 4;          // 0..15 : S row-group (4 rows)
    const int tj = tid & 15;          // 0..15 : S col-group (4 cols)
    const int col = tid & 63;         // for colsum
    const int rg  = tid >> 6;         // 0..3

    float c00=0.f,c01=0.f,c02=0.f,c03=0.f;
    float c10=0.f,c11=0.f,c12=0.f,c13=0.f;
    float c20=0.f,c21=0.f,c22=0.f,c23=0.f;
    float c30=0.f,c31=0.f,c32=0.f,c33=0.f;
    float csum = 0.f;

    for (int tile = blockIdx.x; tile < N_TILES; tile += gridDim.x) {
        __syncthreads();
        const float* xb = x + (size_t)tile * (64 * 63);
        for (int i2 = tid; i2 < 64 * 64; i2 += 256) {
            int r = i2 >> 6, cc = i2 & 63;
            xs[r][cc] = (cc < 63) ? xb[r * 63 + cc] : 0.f;
        }
        __syncthreads();

        // column sums (4 threads per column, disjoint row sets)
        #pragma unroll 4
        for (int r = rg; r < 64; r += 4) csum += xs[r][col];

        // 4x4 outer-product accumulation
        #pragma unroll 4
        for (int r = 0; r < 64; r++) {
            float4 a = *(const float4*)&xs[r][4 * ti];
            float4 b = *(const float4*)&xs[r][4 * tj];
            c00 = fmaf(a.x, b.x, c00); c01 = fmaf(a.x, b.y, c01);
            c02 = fmaf(a.x, b.z, c02); c03 = fmaf(a.x, b.w, c03);
            c10 = fmaf(a.y, b.x, c10); c11 = fmaf(a.y, b.y, c11);
            c12 = fmaf(a.y, b.z, c12); c13 = fmaf(a.y, b.w, c13);
            c20 = fmaf(a.z, b.x, c20); c21 = fmaf(a.z, b.y, c21);
            c22 = fmaf(a.z, b.z, c22); c23 = fmaf(a.z, b.w, c23);
            c30 = fmaf(a.w, b.x, c30); c31 = fmaf(a.w, b.y, c31);
            c32 = fmaf(a.w, b.z, c32); c33 = fmaf(a.w, b.w, c33);
        }
    }

    // reduce colsum partials through smem (reuse xs rows 0..3)
    __syncthreads();
    xs[rg][col] = csum;
    __syncthreads();
    if (tid < 64) {
        float s = xs[0][tid] + xs[1][tid] + xs[2][tid] + xs[3][tid];
        atomicAdd(&g_colsum[tid], (double)s);
    }

    // flush 4x4 tile to global S (double accumulation for accuracy)
    const int rbase = 4 * ti, cbase = 4 * tj;
    atomicAdd(&g_C[(rbase+0)*64 + cbase+0], (double)c00);
    atomicAdd(&g_C[(rbase+0)*64 + cbase+1], (double)c01);
    atomicAdd(&g_C[(rbase+0)*64 + cbase+2], (double)c02);
    atomicAdd(&g_C[(rbase+0)*64 + cbase+3], (double)c03);
    atomicAdd(&g_C[(rbase+1)*64 + cbase+0], (double)c10);
    atomicAdd(&g_C[(rbase+1)*64 + cbase+1], (double)c11);
    atomicAdd(&g_C[(rbase+1)*64 + cbase+2], (double)c12);
    atomicAdd(&g_C[(rbase+1)*64 + cbase+3], (double)c13);
    atomicAdd(&g_C[(rbase+2)*64 + cbase+0], (double)c20);
    atomicAdd(&g_C[(rbase+2)*64 + cbase+1], (double)c21);
    atomicAdd(&g_C[(rbase+2)*64 + cbase+2], (double)c22);
    atomicAdd(&g_C[(rbase+2)*64 + cbase+3], (double)c23);
    atomicAdd(&g_C[(rbase+3)*64 + cbase+0], (double)c30);
    atomicAdd(&g_C[(rbase+3)*64 + cbase+1], (double)c31);
    atomicAdd(&g_C[(rbase+3)*64 + cbase+2], (double)c32);
    atomicAdd(&g_C[(rbase+3)*64 + cbase+3], (double)c33);
}

// ---------------------------------------------------------------------------
// Kernel 2: finalize per-channel BN params from S and colsum.
// mean_d = W_d . xbar ;  E[h^2]_d = W_d^T S W_d / M ; var = E[h^2] - mean^2
// One block per channel d, 64 threads over p.
// ---------------------------------------------------------------------------
__global__ void finalize_kernel(const float* __restrict__ W,
                                const float* __restrict__ gamma,
                                const float* __restrict__ beta) {
    __shared__ double s1[64];
    __shared__ double s2[64];
    const int d = blockIdx.x;
    const int p = threadIdx.x;

    double t1 = 0.0, t2 = 0.0;
    if (p < P_DIM) {
        double wp = (double)W[d * P_DIM + p];
        t1 = wp * g_colsum[p];
        double acc = 0.0;
        for (int q = 0; q < P_DIM; q++)
            acc += (double)W[d * P_DIM + q] * g_C[p * 64 + q];
        t2 = wp * acc;
    }
    s1[p] = t1; s2[p] = t2;
    __syncthreads();
    for (int s = 32; s > 0; s >>= 1) {
        if (p < s) { s1[p] += s1[p + s]; s2[p] += s2[p + s]; }
        __syncthreads();
    }
    if (p == 0) {
        const double inv = 1.0 / (double)M_TOTAL;
        double mean = s1[0] * inv;
        double var  = s2[0] * inv - mean * mean;
        float rsq = (float)(1.0 / sqrt(var + 1e-5));
        g_prm[d] = make_float4((float)mean, rsq, gamma[d], beta[d]);
    }
}

// ---------------------------------------------------------------------------
// Kernel 3: fused GEMM + BatchNorm + 4-step LIF.
// Block: 256 threads handle 64 (b,n)-rows x all 128 channels; loops t=0..3
// with the membrane potential v held in registers across time steps.
// Thread (tR,tC) owns a 4-row x 8-channel tile.
// ---------------------------------------------------------------------------
__global__ __launch_bounds__(256, 2) void lif_main_kernel(
    const float* __restrict__ x,
    const float* __restrict__ W,
    float* __restrict__ out) {
    __shared__ __align__(16) float xs[64][64];     // 16 KB
    __shared__ __align__(16) float Ws[P_DIM][128]; // 31.5 KB, Ws[p][d] = W[d][p]

    const int tid = threadIdx.x;
    const int tR = tid >> 4;     // 0..15 -> rows 4*tR..4*tR+3
    const int tC = tid & 15;     // 0..15 -> channels 8*tC..8*tC+7
    const int row0 = blockIdx.x * 64;

    // stage W transposed into smem (one time per block)
    for (int i = tid; i < D_DIM * P_DIM; i += 256) {
        int d = i / P_DIM, p = i % P_DIM;
        Ws[p][d] = W[i];
    }

    float v[4][8];
    #pragma unroll
    for (int i = 0; i < 4; i++)
        #pragma unroll
        for (int j = 0; j < 8; j++) v[i][j] = 0.f;

    for (int t = 0; t < T_STEPS; t++) {
        __syncthreads();  // also covers the W staging before first use
        const float* xb = x + ((size_t)t * BN_ROWS + row0) * P_DIM;
        for (int i2 = tid; i2 < 64 * 64; i2 += 256) {
            int r = i2 >> 6, cc = i2 & 63;
            xs[r][cc] = (cc < 63) ? xb[r * 63 + cc] : 0.f;
        }
        __syncthreads();

        float acc[4][8];
        #pragma unroll
        for (int i = 0; i < 4; i++)
            #pragma unroll
            for (int j = 0; j < 8; j++) acc[i][j] = 0.f;

        #pragma unroll 3
        for (int k = 0; k < P_DIM; k++) {
            float4 b0 = *(const float4*)&Ws[k][8 * tC];
            float4 b1 = *(const float4*)&Ws[k][8 * tC + 4];
            #pragma unroll
            for (int i = 0; i < 4; i++) {
                float a = xs[4 * tR + i][k];
                acc[i][0] = fmaf(a, b0.x, acc[i][0]);
                acc[i][1] = fmaf(a, b0.y, acc[i][1]);
                acc[i][2] = fmaf(a, b0.z, acc[i][2]);
                acc[i][3] = fmaf(a, b0.w, acc[i][3]);
                acc[i][4] = fmaf(a, b1.x, acc[i][4]);
                acc[i][5] = fmaf(a, b1.y, acc[i][5]);
                acc[i][6] = fmaf(a, b1.z, acc[i][6]);
                acc[i][7] = fmaf(a, b1.w, acc[i][7]);
            }
        }

        // BN + LIF epilogue; write spikes
        #pragma unroll
        for (int i = 0; i < 4; i++) {
            float sv[8];
            #pragma unroll
            for (int j = 0; j < 8; j++) {
                float4 prm = g_prm[8 * tC + j];     // (mean, rsq, gamma, beta)
                float h = (acc[i][j] - prm.x) * prm.y;
                h = h * prm.z + prm.w;
                float vv = v[i][j] + (h - v[i][j]) * 0.5f;        // v + (x-v)/tau
                float s = ((vv - 1.0f) >= 0.0f) ? 1.0f : 0.0f;    // H(v'-1)
                v[i][j] = vv * (1.0f - s);                        // hard reset
                sv[j] = s;
            }
            size_t o = ((size_t)t * BN_ROWS + row0 + 4 * tR + i) * D_DIM + 8 * tC;
            *(float4*)&out[o]     = make_float4(sv[0], sv[1], sv[2], sv[3]);
            *(float4*)&out[o + 4] = make_float4(sv[4], sv[5], sv[6], sv[7]);
        }
    }
}

// ---------------------------------------------------------------------------
extern "C" void kernel_launch(void* const* d_in, const int* in_sizes, int n_in,
                              void* d_out, int out_size) {
    const float* x     = (const float*)d_in[0];   // [4,64,1024,63]
    const float* W     = (const float*)d_in[1];   // [128,63]
    const float* gamma = (const float*)d_in[2];   // [128]
    const float* beta  = (const float*)d_in[3];   // [128]
    // d_in[4] = pe (unused: reference skips the tAPE branch)
    float* out = (float*)d_out;                   // [4,64,1024,128]

    zero_stats_kernel<<<16, 256>>>();
    stats_kernel<<<1024, 256>>>(x);
    finalize_kernel<<<D_DIM, 64>>>(W, gamma, beta);
    lif_main_kernel<<<BN_ROWS / 64, 256>>>(x, W, out);
}

// round 3
// speedup vs baseline: 1.7953x; 1.7953x over previous
#include <cuda_runtime.h>

// Problem constants
#define T_STEPS  4
#define P_DIM    63
#define D_DIM    128
#define BN_ROWS  65536              // B*N = 64*1024
#define M_TOTAL  262144             // T*B*N
#define N_TILES  4096               // M_TOTAL / 64

// Scratch (no allocations allowed -> __device__ globals)
__device__ double g_C[64 * 64];     // S = sum_m x_m x_m^T  (cols 63 padded with zeros)
__device__ double g_colsum[64];     // per-feature column sums of x
__device__ float4 g_prm[D_DIM];     // per-channel (mean, rsqrt(var+eps), gamma, beta)

// ---------------------------------------------------------------------------
// Kernel 0: zero the stat accumulators (must run every launch: graph replays)
// ---------------------------------------------------------------------------
__global__ void zero_stats_kernel() {
    int i = blockIdx.x * blockDim.x + threadIdx.x;
    if (i < 64 * 64) g_C[i] = 0.0;
    if (i < 64)      g_colsum[i] = 0.0;
}

// ---------------------------------------------------------------------------
// Kernel 1: stats pass.  S += X^T X  and colsum += X^T 1 over all M rows.
// (unchanged from passing round-1 kernel)
// ---------------------------------------------------------------------------
__global__ __launch_bounds__(256) void stats_kernel(const float* __restrict__ x) {
    __shared__ __align__(16) float xs[64][64];
    const int tid = threadIdx.x;
    const int ti = tid >> 4;
    const int tj = tid & 15;
    const int col = tid & 63;
    const int rg  = tid >> 6;

    float c00=0.f,c01=0.f,c02=0.f,c03=0.f;
    float c10=0.f,c11=0.f,c12=0.f,c13=0.f;
    float c20=0.f,c21=0.f,c22=0.f,c23=0.f;
    float c30=0.f,c31=0.f,c32=0.f,c33=0.f;
    float csum = 0.f;

    for (int tile = blockIdx.x; tile < N_TILES; tile += gridDim.x) {
        __syncthreads();
        const float* xb = x + (size_t)tile * (64 * 63);
        for (int i2 = tid; i2 < 64 * 64; i2 += 256) {
            int r = i2 >> 6, cc = i2 & 63;
            xs[r][cc] = (cc < 63) ? xb[r * 63 + cc] : 0.f;
        }
        __syncthreads();

        #pragma unroll 4
        for (int r = rg; r < 64; r += 4) csum += xs[r][col];

        #pragma unroll 4
        for (int r = 0; r < 64; r++) {
            float4 a = *(const float4*)&xs[r][4 * ti];
            float4 b = *(const float4*)&xs[r][4 * tj];
            c00 = fmaf(a.x, b.x, c00); c01 = fmaf(a.x, b.y, c01);
            c02 = fmaf(a.x, b.z, c02); c03 = fmaf(a.x, b.w, c03);
            c10 = fmaf(a.y, b.x, c10); c11 = fmaf(a.y, b.y, c11);
            c12 = fmaf(a.y, b.z, c12); c13 = fmaf(a.y, b.w, c13);
            c20 = fmaf(a.z, b.x, c20); c21 = fmaf(a.z, b.y, c21);
            c22 = fmaf(a.z, b.z, c22); c23 = fmaf(a.z, b.w, c23);
            c30 = fmaf(a.w, b.x, c30); c31 = fmaf(a.w, b.y, c31);
            c32 = fmaf(a.w, b.z, c32); c33 = fmaf(a.w, b.w, c33);
        }
    }

    __syncthreads();
    xs[rg][col] = csum;
    __syncthreads();
    if (tid < 64) {
        float s = xs[0][tid] + xs[1][tid] + xs[2][tid] + xs[3][tid];
        atomicAdd(&g_colsum[tid], (double)s);
    }

    const int rbase = 4 * ti, cbase = 4 * tj;
    atomicAdd(&g_C[(rbase+0)*64 + cbase+0], (double)c00);
    atomicAdd(&g_C[(rbase+0)*64 + cbase+1], (double)c01);
    atomicAdd(&g_C[(rbase+0)*64 + cbase+2], (double)c02);
    atomicAdd(&g_C[(rbase+0)*64 + cbase+3], (double)c03);
    atomicAdd(&g_C[(rbase+1)*64 + cbase+0], (double)c10);
    atomicAdd(&g_C[(rbase+1)*64 + cbase+1], (double)c11);
    atomicAdd(&g_C[(rbase+1)*64 + cbase+2], (double)c12);
    atomicAdd(&g_C[(rbase+1)*64 + cbase+3], (double)c13);
    atomicAdd(&g_C[(rbase+2)*64 + cbase+0], (double)c20);
    atomicAdd(&g_C[(rbase+2)*64 + cbase+1], (double)c21);
    atomicAdd(&g_C[(rbase+2)*64 + cbase+2], (double)c22);
    atomicAdd(&g_C[(rbase+2)*64 + cbase+3], (double)c23);
    atomicAdd(&g_C[(rbase+3)*64 + cbase+0], (double)c30);
    atomicAdd(&g_C[(rbase+3)*64 + cbase+1], (double)c31);
    atomicAdd(&g_C[(rbase+3)*64 + cbase+2], (double)c32);
    atomicAdd(&g_C[(rbase+3)*64 + cbase+3], (double)c33);
}

// ---------------------------------------------------------------------------
// Kernel 2: finalize per-channel BN params from S and colsum. (unchanged)
// ---------------------------------------------------------------------------
__global__ void finalize_kernel(const float* __restrict__ W,
                                const float* __restrict__ gamma,
                                const float* __restrict__ beta) {
    __shared__ double s1[64];
    __shared__ double s2[64];
    const int d = blockIdx.x;
    const int p = threadIdx.x;

    double t1 = 0.0, t2 = 0.0;
    if (p < P_DIM) {
        double wp = (double)W[d * P_DIM + p];
        t1 = wp * g_colsum[p];
        double acc = 0.0;
        for (int q = 0; q < P_DIM; q++)
            acc += (double)W[d * P_DIM + q] * g_C[p * 64 + q];
        t2 = wp * acc;
    }
    s1[p] = t1; s2[p] = t2;
    __syncthreads();
    for (int s = 32; s > 0; s >>= 1) {
        if (p < s) { s1[p] += s1[p + s]; s2[p] += s2[p + s]; }
        __syncthreads();
    }
    if (p == 0) {
        const double inv = 1.0 / (double)M_TOTAL;
        double mean = s1[0] * inv;
        double var  = s2[0] * inv - mean * mean;
        float rsq = (float)(1.0 / sqrt(var + 1e-5));
        g_prm[d] = make_float4((float)mean, rsq, gamma[d], beta[d]);
    }
}

// ---------------------------------------------------------------------------
// Kernel 3: fused GEMM + BatchNorm + 4-step LIF.
// 128 threads/block, tile 64 rows x 128 channels, 8x8 register tile/thread.
// Shared layout: xs padded to 65 cols (bank-spread for 8-row broadcast loads);
// W split into Wa/Wb so each LDS.128 reads 16 contiguous 16B chunks
// (conflict-free). v (membrane) lives in registers across t.
// ---------------------------------------------------------------------------
__global__ __launch_bounds__(128, 2) void lif_main_kernel(
    const float* __restrict__ x,
    const float* __restrict__ W,
    float* __restrict__ out) {
    __shared__ __align__(16) float xs[64][65];     // 16.6 KB
    __shared__ __align__(16) float Wa[P_DIM][64];  // 15.75 KB  (ch 8g..8g+3)
    __shared__ __align__(16) float Wb[P_DIM][64];  // 15.75 KB  (ch 8g+4..8g+7)

    const int tid = threadIdx.x;
    const int tR = tid >> 4;     // 0..7  -> rows 8*tR .. 8*tR+7
    const int tC = tid & 15;     // 0..15 -> channels 8*tC .. 8*tC+7
    const int row0 = blockIdx.x * 64;

    // stage W: Wa[k][4g+j] = W[(8g+j)*63+k], Wb[k][4g+j] = W[(8g+4+j)*63+k]
    for (int i = tid; i < P_DIM * 64; i += 128) {
        int k = i >> 6, c = i & 63;
        int g = c >> 2, j = c & 3;
        Wa[k][c] = W[(8 * g + j)     * P_DIM + k];
        Wb[k][c] = W[(8 * g + 4 + j) * P_DIM + k];
    }

    float v[8][8];
    #pragma unroll
    for (int i = 0; i < 8; i++)
        #pragma unroll
        for (int j = 0; j < 8; j++) v[i][j] = 0.f;

    for (int t = 0; t < T_STEPS; t++) {
        __syncthreads();  // also covers the W staging before first use
        const float* xb = x + ((size_t)t * BN_ROWS + row0) * P_DIM;
        for (int i2 = tid; i2 < 64 * P_DIM; i2 += 128) {
            int r = i2 / P_DIM, cc = i2 - r * P_DIM;
            xs[r][cc] = xb[i2];
        }
        __syncthreads();

        float acc[8][8];
        #pragma unroll
        for (int i = 0; i < 8; i++)
            #pragma unroll
            for (int j = 0; j < 8; j++) acc[i][j] = 0.f;

        #pragma unroll 1
        for (int k = 0; k < P_DIM; k++) {
            float4 b0 = *(const float4*)&Wa[k][4 * tC];
            float4 b1 = *(const float4*)&Wb[k][4 * tC];
            float a0 = xs[8 * tR + 0][k];
            float a1 = xs[8 * tR + 1][k];
            float a2 = xs[8 * tR + 2][k];
            float a3 = xs[8 * tR + 3][k];
            float a4 = xs[8 * tR + 4][k];
            float a5 = xs[8 * tR + 5][k];
            float a6 = xs[8 * tR + 6][k];
            float a7 = xs[8 * tR + 7][k];
            float a[8] = {a0, a1, a2, a3, a4, a5, a6, a7};
            #pragma unroll
            for (int i = 0; i < 8; i++) {
                acc[i][0] = fmaf(a[i], b0.x, acc[i][0]);
                acc[i][1] = fmaf(a[i], b0.y, acc[i][1]);
                acc[i][2] = fmaf(a[i], b0.z, acc[i][2]);
                acc[i][3] = fmaf(a[i], b0.w, acc[i][3]);
                acc[i][4] = fmaf(a[i], b1.x, acc[i][4]);
                acc[i][5] = fmaf(a[i], b1.y, acc[i][5]);
                acc[i][6] = fmaf(a[i], b1.z, acc[i][6]);
                acc[i][7] = fmaf(a[i], b1.w, acc[i][7]);
            }
        }

        // BN + LIF epilogue; same arithmetic order as the rel_err=0 kernel.
        #pragma unroll
        for (int i = 0; i < 8; i++) {
            float sv[8];
            #pragma unroll
            for (int j = 0; j < 8; j++) {
                float4 prm = g_prm[8 * tC + j];     // (mean, rsq, gamma, beta)
                float h = (acc[i][j] - prm.x) * prm.y;
                h = h * prm.z + prm.w;
                float vv = v[i][j] + (h - v[i][j]) * 0.5f;        // v + (x-v)/tau
                float s = ((vv - 1.0f) >= 0.0f) ? 1.0f : 0.0f;    // H(v'-1)
                v[i][j] = vv * (1.0f - s);                        // hard reset
                sv[j] = s;
            }
            size_t o = ((size_t)t * BN_ROWS + row0 + 8 * tR + i) * D_DIM + 8 * tC;
            *(float4*)&out[o]     = make_float4(sv[0], sv[1], sv[2], sv[3]);
            *(float4*)&out[o + 4] = make_float4(sv[4], sv[5], sv[6], sv[7]);
        }
    }
}

// ---------------------------------------------------------------------------
extern "C" void kernel_launch(void* const* d_in, const int* in_sizes, int n_in,
                              void* d_out, int out_size) {
    const float* x     = (const float*)d_in[0];   // [4,64,1024,63]
    const float* W     = (const float*)d_in[1];   // [128,63]
    const float* gamma = (const float*)d_in[2];   // [128]
    const float* beta  = (const float*)d_in[3];   // [128]
    float* out = (float*)d_out;                   // [4,64,1024,128]

    zero_stats_kernel<<<16, 256>>>();
    stats_kernel<<<1024, 256>>>(x);
    finalize_kernel<<<D_DIM, 64>>>(W, gamma, beta);
    lif_main_kernel<<<BN_ROWS / 64, 128>>>(x, W, out);
}